// round 14
// baseline (speedup 1.0000x reference)
#include <cuda_runtime.h>
#include <stdint.h>

#define NB      8
#define NPIX    262144
#define NF4     65536
#define NBINS   2048
#define GRID    148               // 1 CTA/SM, all-resident (148 or 152 SM chip)
#define NTHR    288               // 256 consumers (8 warps) + 1 producer warp
#define NTILES  2048              // 1024 px per tile
#define TPX     1024
#define NSTG    4
#define STGB    49152             // 48KB per stage
#define MARGIN  4500
#define SCALE_D 65535.0f
#define SCALE_C 21845.0f

__device__ uint4    g_pk   [NB * NF4];      // 8MB packed bf16x2 (stays L2-resident)
__device__ unsigned g_hist1[2][NB][NBINS];
__device__ unsigned g_win  [2][NB][NBINS];
__device__ float    g_wsum [2][NB][NBINS];
__device__ unsigned g_cntU [NB];
__device__ float    g_Sab  [2][NB];
__device__ unsigned g_Cab  [2][NB];
__device__ int      g_wlo  [2][NB];
__device__ int      g_whi  [2][NB];
__device__ unsigned g_bar  [4];             // monotonic epoch counters (never reset)

__device__ __forceinline__ unsigned f2bf(float f) {
    unsigned u = __float_as_uint(f);
    return (u + 0x7FFFu + ((u >> 16) & 1u)) >> 16;
}
__device__ __forceinline__ float bf2f(unsigned b) { return __uint_as_float(b << 16); }
__device__ __forceinline__ int   qkey(float v, float s) {
    int q = (int)(v * s);
    return q > 65535 ? 65535 : q;
}
__device__ __forceinline__ float pget(const float4& v, int p) { return p == 0 ? v.x : p == 1 ? v.y : p == 2 ? v.z : v.w; }
__device__ __forceinline__ int   tget(const int4&   v, int p) { return p == 0 ? v.x : p == 1 ? v.y : p == 2 ? v.z : v.w; }

__device__ __forceinline__ unsigned s2u(const void* p) {
    unsigned r;
    asm("{ .reg .u64 t; cvta.to.shared.u64 t, %1; cvt.u32.u64 %0, t; }" : "=r"(r) : "l"(p));
    return r;
}
#define MB_INIT(mb, cntv) \
    asm volatile("mbarrier.init.shared.b64 [%0], %1;" :: "r"(mb), "r"(cntv) : "memory")
#define MB_EXPECT(mb, bytes) \
    asm volatile("mbarrier.arrive.expect_tx.shared.b64 _, [%0], %1;" :: "r"(mb), "r"(bytes) : "memory")
#define MB_ARRIVE(mb) \
    asm volatile("mbarrier.arrive.shared.b64 _, [%0];" :: "r"(mb) : "memory")
__device__ __forceinline__ void mb_wait(unsigned mb, unsigned ph) {
    unsigned done = 0;
    while (!done)
        asm volatile("{ .reg .pred p; mbarrier.try_wait.parity.acquire.cta.shared::cta.b64 p, [%1], %2; selp.b32 %0, 1, 0, p; }"
                     : "=r"(done) : "r"(mb), "r"(ph) : "memory");
}
#define BULK_CP(dst, src, mb) \
    asm volatile("cp.async.bulk.shared::cluster.global.mbarrier::complete_tx::bytes [%0], [%1], %2, [%3];" \
                 :: "r"(dst), "l"(src), "n"(4096), "r"(mb) : "memory")

__device__ __forceinline__ void grid_barrier(int id) {
    __syncthreads();
    if (threadIdx.x == 0) {
        __threadfence();
        unsigned old = atomicAdd(&g_bar[id], 1u);
        unsigned target = old - (old % GRID) + GRID;
        while (*((volatile unsigned*)&g_bar[id]) < target) __nanosleep(128);
        __threadfence();
    }
    __syncthreads();
}

extern __shared__ char dsm[];               // NSTG * STGB = 192KB staging ring

__global__ void __launch_bounds__(NTHR, 1)
kFused(const char* __restrict__ img, const char* __restrict__ alp,
       const char* __restrict__ prd, const char* __restrict__ tri,
       const char* __restrict__ fg,  const char* __restrict__ bg,
       float* out)
{
    __shared__ __align__(8) unsigned long long s_mb[8];   // full[0..3], empty[4..7]
    __shared__ unsigned wt[8];
    __shared__ float    wtf[8];
    __shared__ int      s_hi[2][8], s_lo[2][8], s_wl[2][8];

    const int t   = threadIdx.x;
    const int l   = t & 31, w = t >> 5;
    const int blk = blockIdx.x;
    const unsigned mbF = s2u(&s_mb[0]);
    const unsigned mbE = s2u(&s_mb[4]);
    const unsigned smB = s2u(dsm);

    if (t == 0) {
        if (blk == 0) out[0] = 0.0f;
#pragma unroll
        for (int s = 0; s < NSTG; s++) { MB_INIT(mbF + s * 8, 1); MB_INIT(mbE + s * 8, 256); }
    }
    __syncthreads();

    // ================= PHASE 1: TMA pipeline ================================
    if (t == 256) {
        // ---- producer: one thread streams 12x4KB bulk copies per tile ----
        int n = 0;
        for (int T = blk; T < NTILES; T += GRID, n++) {
            int s = n & 3;
            mb_wait(mbE + s * 8, 1u ^ ((unsigned)(n >> 2) & 1u));
            MB_EXPECT(mbF + s * 8, (unsigned)STGB);
            int b  = T >> 8, tl = T & 255;
            size_t o1 = ((size_t)b * NPIX + (size_t)tl * TPX) * 4;
            unsigned d = smB + s * STGB;
            BULK_CP(d,         tri + o1, mbF + s * 8);
            BULK_CP(d + 4096,  alp + o1, mbF + s * 8);
            BULK_CP(d + 8192,  prd + o1, mbF + s * 8);
#pragma unroll
            for (int c = 0; c < 3; c++) {
                size_t o3 = ((size_t)(b * 3 + c) * NPIX + (size_t)tl * TPX) * 4;
                BULK_CP(d + 12288 + c * 4096, img + o3, mbF + s * 8);
                BULK_CP(d + 24576 + c * 4096, fg  + o3, mbF + s * 8);
                BULK_CP(d + 36864 + c * 4096, bg  + o3, mbF + s * 8);
            }
        }
    } else if (t < 256) {
        // ---- consumers: 256 threads, 1 float4-group each per tile ----
        const float inv255 = 1.0f / 255.0f;
        int n = 0;
        for (int T = blk; T < NTILES; T += GRID, n++) {
            int s = n & 3;
            mb_wait(mbF + s * 8, (unsigned)(n >> 2) & 1u);
            const char* sb = dsm + s * STGB;
            const int4   tv = *(const int4*)  (sb          + t * 16);
            const float4 av = *(const float4*)(sb + 4096   + t * 16);
            const float4 pv = *(const float4*)(sb + 8192   + t * 16);
            const float4 i0 = *(const float4*)(sb + 12288  + t * 16);
            const float4 i1 = *(const float4*)(sb + 16384  + t * 16);
            const float4 i2 = *(const float4*)(sb + 20480  + t * 16);
            const float4 f0 = *(const float4*)(sb + 24576  + t * 16);
            const float4 f1 = *(const float4*)(sb + 28672  + t * 16);
            const float4 f2 = *(const float4*)(sb + 32768  + t * 16);
            const float4 g0 = *(const float4*)(sb + 36864  + t * 16);
            const float4 g1 = *(const float4*)(sb + 40960  + t * 16);
            const float4 g2 = *(const float4*)(sb + 45056  + t * 16);

            unsigned pk[4]; unsigned cnt = 0;
            float d0s = 0.f, dc0s = 0.f; bool u0 = false;
#pragma unroll
            for (int p = 0; p < 4; p++) {
                bool ub = (tget(tv, p) == 128);
                float m  = ub ? 1.0f : 0.0f;
                float pr = pget(pv, p), q = 1.0f - pr;
                float d  = fabsf(fmaf(pget(av, p), inv255, -pr)) * m;
                float dc = (fabsf(pget(i0, p) - (pget(f0, p) * pr + q * pget(g0, p)))
                          + fabsf(pget(i1, p) - (pget(f1, p) * pr + q * pget(g1, p)))
                          + fabsf(pget(i2, p) - (pget(f2, p) * pr + q * pget(g2, p)))) * m;
                cnt += ub ? 1u : 0u;
                if (p == 0) { u0 = ub; d0s = d; dc0s = dc; }
                pk[p] = f2bf(d) | (f2bf(dc) << 16);
            }
            MB_ARRIVE(mbE + s * 8);            // smem values consumed; release stage

            int b = T >> 8;
            g_pk[T * 256 + t] = make_uint4(pk[0], pk[1], pk[2], pk[3]);
            if (u0) {                          // 1/4 subsample, spread linear-key REDG
                atomicAdd(&g_hist1[0][b][qkey(d0s,  SCALE_D) >> 5], 1u);
                atomicAdd(&g_hist1[1][b][qkey(dc0s, SCALE_C) >> 5], 1u);
            }
            for (int o = 16; o; o >>= 1) cnt += __shfl_down_sync(0xffffffffu, cnt, o);
            if (l == 0 && cnt) atomicAdd(&g_cntU[b], cnt);
        }
    }

    grid_barrier(0);

    // ================= SELECT (blocks 0..15) ================================
    {
        bool selB = (blk < 16);
        int a = blk >> 3, bb = blk & 7;
        unsigned count = selB ? g_cntU[bb] : 0u;
        int k = (int)floorf((float)count * 0.7f);
        unsigned harr[8]; unsigned loc = 0;
        if (selB && t < 256) {
#pragma unroll
            for (int jj = 0; jj < 8; jj++) { harr[jj] = g_hist1[a][bb][t * 8 + jj]; loc += harr[jj]; }
        } else {
#pragma unroll
            for (int jj = 0; jj < 8; jj++) harr[jj] = 0;
        }
        unsigned s = loc;
#pragma unroll
        for (int o = 1; o < 32; o <<= 1) {     // warp inclusive suffix scan
            unsigned v = __shfl_down_sync(0xffffffffu, s, o);
            if (l + o < 32) s += v;
        }
        if (l == 0 && w < 8) wt[w] = s;
        __syncthreads();
        if (selB && t < 256) {
            unsigned wsuf = 0;
            for (int w2 = w + 1; w2 < 8; w2++) wsuf += wt[w2];
            int acc = (int)(wsuf + (s - loc));
            if (k > 0) {
                int tLo = k + MARGIN;
                int tHi = max(k - MARGIN, 1);
#pragma unroll
                for (int jj = 7; jj >= 0; jj--) {
                    int i = t * 8 + jj;
                    int c = (int)harr[jj];
                    int above  = 4 * acc;
                    int aboveP = 4 * (acc + c);
                    if (above < tLo && (i == 0 || aboveP >= tLo)) g_wlo[a][bb] = i;
                    if (above < tHi && (i == 0 || aboveP >= tHi)) g_whi[a][bb] = i;
                    acc += c;
                }
            } else if (t == 0) {
                g_wlo[a][bb] = 2047; g_whi[a][bb] = -1;
            }
        }
    }

    grid_barrier(1);

    // ================= WINDOW PASS (all blocks, g_pk is L2-hot) =============
    if (t < 16) {
        int a = t >> 3, bb = t & 7;
        int wlo = g_wlo[a][bb], whi = g_whi[a][bb];
        s_wl[a][bb] = wlo;
        s_lo[a][bb] = max(wlo << 5, 1);
        s_hi[a][bb] = (whi + 1) << 5;
    }
    __syncthreads();

    if (t < 256) {
        for (int T = blk; T < NTILES; T += GRID) {
            int b = T >> 8;
            const int hiD = s_hi[0][b], loD = s_lo[0][b], wlD = s_wl[0][b];
            const int hiC = s_hi[1][b], loC = s_lo[1][b], wlC = s_wl[1][b];
            uint4 pv4 = g_pk[T * 256 + t];
            unsigned pk4[4] = { pv4.x, pv4.y, pv4.z, pv4.w };
            float s0 = 0.f, s1 = 0.f; unsigned c0 = 0, c1 = 0;
#pragma unroll
            for (int p = 0; p < 4; p++) {
                float vd = bf2f(pk4[p] & 0xFFFFu);
                float vc = bf2f(pk4[p] >> 16);
                int kqd = qkey(vd, SCALE_D);
                int kqc = qkey(vc, SCALE_C);
                if (kqd >= hiD) { s0 += vd; c0++; }
                else if (kqd >= loD) {
                    int idx = (kqd >> 5) - wlD;
                    atomicAdd(&g_win[0][b][idx], 1u);
                    atomicAdd(&g_wsum[0][b][idx], vd);
                }
                if (kqc >= hiC) { s1 += vc; c1++; }
                else if (kqc >= loC) {
                    int idx = (kqc >> 5) - wlC;
                    atomicAdd(&g_win[1][b][idx], 1u);
                    atomicAdd(&g_wsum[1][b][idx], vc);
                }
            }
            for (int o = 16; o; o >>= 1) {
                s0 += __shfl_down_sync(0xffffffffu, s0, o);
                s1 += __shfl_down_sync(0xffffffffu, s1, o);
                c0 += __shfl_down_sync(0xffffffffu, c0, o);
                c1 += __shfl_down_sync(0xffffffffu, c1, o);
            }
            if (l == 0) {
                if (s0 != 0.f) atomicAdd(&g_Sab[0][b], s0);
                if (s1 != 0.f) atomicAdd(&g_Sab[1][b], s1);
                if (c0)        atomicAdd(&g_Cab[0][b], c0);
                if (c1)        atomicAdd(&g_Cab[1][b], c1);
            }
        }
    }

    grid_barrier(2);

    // ================= FINALIZE (blocks 0..15) / hist cleanup (others) ======
    if (blk >= 16) {
        int gid = (blk - 16) * NTHR + t;
        if (gid < 2 * NB * NBINS) ((unsigned*)g_hist1)[gid] = 0u;
        return;
    }
    {
        int a = blk >> 3, bb = blk & 7;
        unsigned cc = g_cntU[bb];
        int kk = (int)floorf((float)cc * 0.7f);
        unsigned harr[8]; float hars[8];
        if (t < 256) {
#pragma unroll
            for (int jj = 0; jj < 8; jj++) {
                int i = t * 8 + jj;
                harr[jj] = g_win[a][bb][i];
                hars[jj] = g_wsum[a][bb][i];
                g_win[a][bb][i] = 0u;          // self-clean for next replay
                g_wsum[a][bb][i] = 0.f;
            }
        } else {
#pragma unroll
            for (int jj = 0; jj < 8; jj++) { harr[jj] = 0; hars[jj] = 0.f; }
        }
        unsigned lc = 0; float lv = 0.f;
#pragma unroll
        for (int jj = 0; jj < 8; jj++) { lc += harr[jj]; lv += hars[jj]; }
        unsigned sc = lc; float sv = lv;
#pragma unroll
        for (int o = 1; o < 32; o <<= 1) {
            unsigned vc2 = __shfl_down_sync(0xffffffffu, sc, o);
            float    vv2 = __shfl_down_sync(0xffffffffu, sv, o);
            if (l + o < 32) { sc += vc2; sv += vv2; }
        }
        if (l == 0 && w < 8) { wt[w] = sc; wtf[w] = sv; }
        __syncthreads();
        if (kk > 0 && t < 256) {
            unsigned wsufC = 0; float wsufS = 0.f;
            for (int w2 = w + 1; w2 < 8; w2++) { wsufC += wt[w2]; wsufS += wtf[w2]; }
            unsigned acc  = wsufC + (sc - lc);
            float    accS = wsufS + (sv - lv);
            unsigned Cab = g_Cab[a][bb];
            float    Sab = g_Sab[a][bb];
#pragma unroll
            for (int jj = 7; jj >= 0; jj--) {
                unsigned c = harr[jj];
                unsigned ta = Cab + acc;       // exact count above entry
                if (c > 0 && ta < (unsigned)kk && ta + c >= (unsigned)kk) {
                    float mean = hars[jj] / (float)c;
                    float S = Sab + accS + (float)((unsigned)kk - ta) * mean;
                    atomicAdd(out, 0.0625f * (S / ((float)kk + 1e-6f)));  // 0.5*loss/8
                }
                acc += c; accS += hars[jj];
            }
        }
        __syncthreads();
        if (t == 0) {                          // self-clean scalars
            g_Sab[a][bb] = 0.f; g_Cab[a][bb] = 0u;
            if (a == 0) g_cntU[bb] = 0u;
        }
    }
}

extern "C" void kernel_launch(void* const* d_in, const int* in_sizes, int n_in,
                              void* d_out, int out_size) {
    cudaFuncSetAttribute(kFused, cudaFuncAttributeMaxDynamicSharedMemorySize, NSTG * STGB);
    kFused<<<GRID, NTHR, NSTG * STGB>>>(
        (const char*)d_in[0], (const char*)d_in[1], (const char*)d_in[2],
        (const char*)d_in[3], (const char*)d_in[4], (const char*)d_in[5],
        (float*)d_out);
}